// round 11
// baseline (speedup 1.0000x reference)
#include <cuda_runtime.h>
#include <stdint.h>

// carry_save_adder: exact-binary reduction.
// S_b = sum over kept i of value(x[b,i,:]); out bits = S_b & 0xFFFF, carry = S_b >> 16.
// Persistent SINGLE-WAVE grid (608 CTAs = 4x512thr/SM) with CONTIGUOUS
// per-CTA slices: CTA b sequentially consumes tiles [b*T/G, (b+1)*T/G).
// Zero wave transitions + per-warp sequential streams (page locality).
// Loads: ld.global.nc + L2::256B + evict_first. FFMA-imm nibble math, exact fp32.

#define NCTA 608   // 152 SMs * 4 CTAs (512 thr) = full occupancy, one wave

__device__ __forceinline__ float4 ldg_stream(const float4* p, unsigned long long pol) {
    float4 v;
    asm("ld.global.nc.L2::cache_hint.L2::256B.v4.f32 {%0,%1,%2,%3}, [%4], %5;"
        : "=f"(v.x), "=f"(v.y), "=f"(v.z), "=f"(v.w)
        : "l"(p), "l"(pol));
    return v;
}

__global__ void __launch_bounds__(512)
csa_kernel(const float4* __restrict__ x, const int* __restrict__ mask,
           float* __restrict__ out, int B)
{
    const unsigned FULL = 0xFFFFFFFFu;
    const int lane = threadIdx.x & 31;
    const int wib  = threadIdx.x >> 5;              // 0..15

    // Contiguous tile range for this CTA (tile = 16 rows = 64KB).
    const int ntiles = B >> 4;
    const int t0 = (int)(((long)blockIdx.x       * ntiles) / gridDim.x);
    const int t1 = (int)(((long)(blockIdx.x + 1) * ntiles) / gridDim.x);

    unsigned long long pol;
    asm("createpolicy.fractional.L2::evict_first.b64 %0, 1.0;" : "=l"(pol));

    // Keep mask over the 64 values (indices 0,1 always kept).
    const unsigned mb_lo = __ballot_sync(FULL, mask[lane]      > 0) | 3u;
    const unsigned mb_hi = __ballot_sync(FULL, mask[lane + 32] > 0);

    // Chunk t of this lane holds value index i = 8t + (lane>>2); keep weight:
    const unsigned q = (unsigned)lane >> 2;
    float keepf[8];
    #pragma unroll
    for (int t = 0; t < 8; ++t) {
        unsigned bit = (t < 4) ? ((mb_lo >> (8 * t + q)) & 1u)
                               : ((mb_hi >> (8 * (t - 4) + q)) & 1u);
        keepf[t] = bit ? 1.0f : 0.0f;
    }
    // Loop-invariant nibble weight 2^((lane&3)*4).
    const float wgt = __int_as_float((127 + (((int)lane & 3) << 2)) << 23);

    for (int tile = t0; tile < t1; ++tile) {
        const int row = (tile << 4) + wib;
        const float4* r = x + (size_t)row * 256;

        float sumf = 0.0f;
        #pragma unroll
        for (int t = 0; t < 8; ++t) {
            float4 v = ldg_stream(&r[lane + (t << 5)], pol);
            float part = v.x;
            part = fmaf(v.y, 2.0f, part);
            part = fmaf(v.z, 4.0f, part);
            part = fmaf(v.w, 8.0f, part);
            sumf = fmaf(part, keepf[t], sumf);
        }
        sumf *= wgt;

        // Warp reduction (exact: integer-valued floats, total < 2^22).
        #pragma unroll
        for (int off = 16; off; off >>= 1)
            sumf += __shfl_xor_sync(FULL, sumf, off);

        const unsigned s = (unsigned)sumf;
        if (lane < 16)
            out[(size_t)row * 16 + lane] = (float)((s >> lane) & 1u);
        else if (lane == 16)
            out[(size_t)B * 16 + row] = (float)(s >> 16);
    }
}

extern "C" void kernel_launch(void* const* d_in, const int* in_sizes, int n_in,
                              void* d_out, int out_size)
{
    const float4* x   = (const float4*)d_in[0];   // (B, 64, 16) float32
    const int*    msk = (const int*)d_in[1];      // (64,) int32
    float*        out = (float*)d_out;            // B*16 output bits, then B carries

    int B = in_sizes[0] / 1024;                   // 64*16 floats per batch row

    int ntiles = B / 16;
    int grid = NCTA < ntiles ? NCTA : ntiles;
    csa_kernel<<<grid, 512>>>(x, msk, out, B);
}

// round 12
// speedup vs baseline: 1.0817x; 1.0817x over previous
#include <cuda_runtime.h>
#include <stdint.h>

// carry_save_adder: exact-binary reduction.
// S_b = sum over kept i of value(x[b,i,:]); out bits = S_b & 0xFFFF, carry = S_b >> 16.
// R8 structure (non-persistent in-order CTAs, 512 thr = 16 rows/CTA, warp/row)
// upgraded to 256-bit loads (ld.global.nc.v8.f32, sm_100+): 4 requests per
// lane instead of 8 — half the L1tex wavefronts, perfect 256B DRAM packing.
// Lane l, load t covers floats [256t + 8l, 256t + 8l + 8) of its row:
//   value index i = 16t + (l>>1), bit weights 1..128, times 2^(8*(l&1)).
// All-FFMA-imm accumulation, exact fp32 (S < 2^22).

__device__ __forceinline__ void ldg_nc_v8(const float* p, float* v) {
    asm("ld.global.nc.L2::256B.v8.f32 {%0,%1,%2,%3,%4,%5,%6,%7}, [%8];"
        : "=f"(v[0]), "=f"(v[1]), "=f"(v[2]), "=f"(v[3]),
          "=f"(v[4]), "=f"(v[5]), "=f"(v[6]), "=f"(v[7])
        : "l"(p));
}

__global__ void __launch_bounds__(512)
csa_kernel(const float* __restrict__ x, const int* __restrict__ mask,
           float* __restrict__ out, int B)
{
    const unsigned FULL = 0xFFFFFFFFu;
    const int lane = threadIdx.x & 31;
    const int warp = (blockIdx.x << 4) + (threadIdx.x >> 5);
    if (warp >= B) return;

    // Keep mask over the 64 values (indices 0,1 always kept).
    const unsigned mb_lo = __ballot_sync(FULL, mask[lane]      > 0) | 3u;
    const unsigned mb_hi = __ballot_sync(FULL, mask[lane + 32] > 0);

    // Load t covers value index i = 16t + (lane>>1).
    const unsigned h = (unsigned)lane >> 1;
    float keepf[4];
    #pragma unroll
    for (int t = 0; t < 4; ++t) {
        unsigned bit = (t < 2) ? ((mb_lo >> (16 * t + h)) & 1u)
                               : ((mb_hi >> (16 * (t - 2) + h)) & 1u);
        keepf[t] = bit ? 1.0f : 0.0f;
    }
    // Loop-invariant byte weight 2^(8*(lane&1)).
    const float wgt = (lane & 1) ? 256.0f : 1.0f;

    const float* row = x + (size_t)warp * 1024;

    float sumf = 0.0f;
    #pragma unroll
    for (int t = 0; t < 4; ++t) {
        float v[8];
        ldg_nc_v8(row + 256 * t + 8 * lane, v);
        float part = v[0];
        part = fmaf(v[1],   2.0f, part);
        part = fmaf(v[2],   4.0f, part);
        part = fmaf(v[3],   8.0f, part);
        part = fmaf(v[4],  16.0f, part);
        part = fmaf(v[5],  32.0f, part);
        part = fmaf(v[6],  64.0f, part);
        part = fmaf(v[7], 128.0f, part);
        sumf = fmaf(part, keepf[t], sumf);
    }
    sumf *= wgt;

    // Warp reduction (exact: integer-valued floats, total < 2^22).
    #pragma unroll
    for (int off = 16; off; off >>= 1)
        sumf += __shfl_xor_sync(FULL, sumf, off);

    const unsigned s = (unsigned)sumf;
    if (lane < 16)
        out[(size_t)warp * 16 + lane] = (float)((s >> lane) & 1u);
    else if (lane == 16)
        out[(size_t)B * 16 + warp] = (float)(s >> 16);
}

extern "C" void kernel_launch(void* const* d_in, const int* in_sizes, int n_in,
                              void* d_out, int out_size)
{
    const float* x   = (const float*)d_in[0];   // (B, 64, 16) float32
    const int*   msk = (const int*)d_in[1];     // (64,) int32
    float*       out = (float*)d_out;           // B*16 output bits, then B carries

    int B = in_sizes[0] / 1024;                 // 64*16 floats per batch row
    int blocks = (B + 15) / 16;                 // 16 rows per 512-thread CTA
    csa_kernel<<<blocks, 512>>>(x, msk, out, B);
}